// round 1
// baseline (speedup 1.0000x reference)
#include <cuda_runtime.h>

// ---------------------------------------------------------------------------
// AttentionEncoderLayer: B=4, C=8, F=2048, H=512, NH=8, dh=64, Hf=1024
// All reference reshapes are pure reinterpretations, so:
//   M = F*B = 8192 query rows (query flat [8192,512])
//   key/value flat [65536,512]; query row m attends KV rows [8m, 8m+8)
//   output flat [8192,512] in the same row order.
// Pipeline:
//   Qp = query @ Wq^T + bq
//   Kp = key   @ Wk^T + bk      Vp = value @ Wv^T + bv
//   attn[m] = softmax(Qp_h . Kp_h / 8) @ Vp_h   (per head h, S=8)
//   x  = attn @ Wo^T + bo ; h1 = LN(query + x)
//   f1 = relu(h1 @ W1^T + b1) ; x2 = f1 @ W2^T + b2 ; out = LN(h1 + x2)
// ---------------------------------------------------------------------------

#define M_Q   8192
#define M_KV  65536
#define Hdim  512
#define HF    1024

__device__ float g_Qp [M_Q  * Hdim];
__device__ float g_Kp [M_KV * Hdim];
__device__ float g_Vp [M_KV * Hdim];
__device__ float g_att[M_Q  * Hdim];
__device__ float g_x  [M_Q  * Hdim];
__device__ float g_h1 [M_Q  * Hdim];
__device__ float g_f1 [M_Q  * HF  ];

// ---------------------------------------------------------------------------
// GEMM: C[M,N] = A[M,K] @ W[N,K]^T + bias, optional relu.
// BM=BN=64, BK=16, 256 threads, 4x4 per thread, packed f32x2 FMA inner loop.
// A tile stored DUPLICATED in smem so the mainloop needs no pack instructions.
// Requires M%64==0, N%64==0, K%16==0 (true for all shapes here).
// ---------------------------------------------------------------------------
__global__ __launch_bounds__(256)
void gemm_bias_kernel(const float* __restrict__ A, const float* __restrict__ W,
                      const float* __restrict__ bias, float* __restrict__ C,
                      int M, int N, int K, int relu)
{
    __shared__ float Ad[16][128];   // Ad[k][2m] = Ad[k][2m+1] = A[m0+m][k0+k]
    __shared__ float Bs[16][64];    // Bs[k][n]  = W[n0+n][k0+k]

    const int tid = threadIdx.x;
    const int tx  = tid & 15;       // 0..15 -> 4 N cols
    const int ty  = tid >> 4;       // 0..15 -> 4 M rows
    const int m0  = blockIdx.y * 64;
    const int n0  = blockIdx.x * 64;

    const int lrow = tid >> 2;          // 0..63
    const int lc4  = (tid & 3) * 4;     // 0,4,8,12

    unsigned long long acc[4][2];
#pragma unroll
    for (int i = 0; i < 4; i++) { acc[i][0] = 0ull; acc[i][1] = 0ull; }

    const float* Aptr = A + (size_t)(m0 + lrow) * K + lc4;
    const float* Wptr = W + (size_t)(n0 + lrow) * K + lc4;

    for (int k0 = 0; k0 < K; k0 += 16) {
        float4 av = *(const float4*)(Aptr + k0);
        float4 wv = *(const float4*)(Wptr + k0);
        __syncthreads();
        ((float2*)Ad[lc4 + 0])[lrow] = make_float2(av.x, av.x);
        ((float2*)Ad[lc4 + 1])[lrow] = make_float2(av.y, av.y);
        ((float2*)Ad[lc4 + 2])[lrow] = make_float2(av.z, av.z);
        ((float2*)Ad[lc4 + 3])[lrow] = make_float2(av.w, av.w);
        Bs[lc4 + 0][lrow] = wv.x;
        Bs[lc4 + 1][lrow] = wv.y;
        Bs[lc4 + 2][lrow] = wv.z;
        Bs[lc4 + 3][lrow] = wv.w;
        __syncthreads();
#pragma unroll
        for (int k = 0; k < 16; k++) {
            ulonglong2 a01 = *(const ulonglong2*)&Ad[k][ty * 8];
            ulonglong2 a23 = *(const ulonglong2*)&Ad[k][ty * 8 + 4];
            ulonglong2 b   = *(const ulonglong2*)&Bs[k][tx * 4];
            asm("fma.rn.f32x2 %0,%1,%2,%0;" : "+l"(acc[0][0]) : "l"(a01.x), "l"(b.x));
            asm("fma.rn.f32x2 %0,%1,%2,%0;" : "+l"(acc[0][1]) : "l"(a01.x), "l"(b.y));
            asm("fma.rn.f32x2 %0,%1,%2,%0;" : "+l"(acc[1][0]) : "l"(a01.y), "l"(b.x));
            asm("fma.rn.f32x2 %0,%1,%2,%0;" : "+l"(acc[1][1]) : "l"(a01.y), "l"(b.y));
            asm("fma.rn.f32x2 %0,%1,%2,%0;" : "+l"(acc[2][0]) : "l"(a23.x), "l"(b.x));
            asm("fma.rn.f32x2 %0,%1,%2,%0;" : "+l"(acc[2][1]) : "l"(a23.x), "l"(b.y));
            asm("fma.rn.f32x2 %0,%1,%2,%0;" : "+l"(acc[3][0]) : "l"(a23.y), "l"(b.x));
            asm("fma.rn.f32x2 %0,%1,%2,%0;" : "+l"(acc[3][1]) : "l"(a23.y), "l"(b.y));
        }
    }

    const float4 b4 = *(const float4*)&bias[n0 + tx * 4];
#pragma unroll
    for (int i = 0; i < 4; i++) {
        float2 p0 = *(float2*)&acc[i][0];
        float2 p1 = *(float2*)&acc[i][1];
        float4 r = make_float4(p0.x + b4.x, p0.y + b4.y, p1.x + b4.z, p1.y + b4.w);
        if (relu) {
            r.x = fmaxf(r.x, 0.f); r.y = fmaxf(r.y, 0.f);
            r.z = fmaxf(r.z, 0.f); r.w = fmaxf(r.w, 0.f);
        }
        *(float4*)&C[(size_t)(m0 + ty * 4 + i) * N + n0 + tx * 4] = r;
    }
}

// ---------------------------------------------------------------------------
// Attention: one block per query row m (8192), warp w = head h (8 heads).
// Each lane handles dims {l, l+32} of its head's 64-dim slice.
// S = 8 keys: rows m*8+c of Kp/Vp.  scale = 1/sqrt(64) = 0.125
// ---------------------------------------------------------------------------
__global__ __launch_bounds__(256)
void attn_kernel(const float* __restrict__ Qp, const float* __restrict__ Kp,
                 const float* __restrict__ Vp, float* __restrict__ out)
{
    const int m = blockIdx.x;
    const int w = threadIdx.x >> 5;   // head
    const int l = threadIdx.x & 31;

    const size_t qoff = (size_t)m * Hdim + w * 64;
    const float q0 = Qp[qoff + l];
    const float q1 = Qp[qoff + l + 32];

    float s[8];
#pragma unroll
    for (int c = 0; c < 8; c++) {
        const float* k = Kp + ((size_t)m * 8 + c) * Hdim + w * 64;
        float p = q0 * k[l] + q1 * k[l + 32];
#pragma unroll
        for (int o = 16; o > 0; o >>= 1)
            p += __shfl_xor_sync(0xffffffffu, p, o);
        s[c] = p * 0.125f;
    }

    float mx = s[0];
#pragma unroll
    for (int c = 1; c < 8; c++) mx = fmaxf(mx, s[c]);
    float sum = 0.f;
#pragma unroll
    for (int c = 0; c < 8; c++) { s[c] = __expf(s[c] - mx); sum += s[c]; }
    const float inv = 1.f / sum;

    float o0 = 0.f, o1 = 0.f;
#pragma unroll
    for (int c = 0; c < 8; c++) {
        const float* v = Vp + ((size_t)m * 8 + c) * Hdim + w * 64;
        const float p = s[c] * inv;
        o0 += p * v[l];
        o1 += p * v[l + 32];
    }
    out[qoff + l]      = o0;
    out[qoff + l + 32] = o1;
}

// ---------------------------------------------------------------------------
// LayerNorm(x + r) over H=512, one block (256 threads) per row.
// Matches reference: (s - mean) / sqrt(var + 1e-5) * g + b
// ---------------------------------------------------------------------------
__global__ __launch_bounds__(256)
void ln_residual_kernel(const float* __restrict__ x, const float* __restrict__ r,
                        const float* __restrict__ g, const float* __restrict__ bt,
                        float* __restrict__ out)
{
    __shared__ float red[256];
    const int m = blockIdx.x;
    const int t = threadIdx.x;
    const size_t base = (size_t)m * Hdim;

    const float s0 = x[base + t]       + r[base + t];
    const float s1 = x[base + t + 256] + r[base + t + 256];

    red[t] = s0 + s1;
    __syncthreads();
#pragma unroll
    for (int o = 128; o > 0; o >>= 1) {
        if (t < o) red[t] += red[t + o];
        __syncthreads();
    }
    const float mean = red[0] * (1.f / 512.f);
    __syncthreads();

    const float d0 = s0 - mean, d1 = s1 - mean;
    red[t] = d0 * d0 + d1 * d1;
    __syncthreads();
#pragma unroll
    for (int o = 128; o > 0; o >>= 1) {
        if (t < o) red[t] += red[t + o];
        __syncthreads();
    }
    const float var  = red[0] * (1.f / 512.f);
    const float rstd = rsqrtf(var + 1e-5f);

    out[base + t]       = d0 * rstd * g[t]       + bt[t];
    out[base + t + 256] = d1 * rstd * g[t + 256] + bt[t + 256];
}

// ---------------------------------------------------------------------------
extern "C" void kernel_launch(void* const* d_in, const int* in_sizes, int n_in,
                              void* d_out, int out_size)
{
    (void)in_sizes; (void)n_in; (void)out_size;
    const float* query = (const float*)d_in[0];
    const float* key   = (const float*)d_in[1];
    const float* value = (const float*)d_in[2];
    const float* Wq    = (const float*)d_in[3];
    const float* bq    = (const float*)d_in[4];
    const float* Wk    = (const float*)d_in[5];
    const float* bk    = (const float*)d_in[6];
    const float* Wv    = (const float*)d_in[7];
    const float* bv    = (const float*)d_in[8];
    const float* Wo    = (const float*)d_in[9];
    const float* bo    = (const float*)d_in[10];
    const float* ln1g  = (const float*)d_in[11];
    const float* ln1b  = (const float*)d_in[12];
    const float* W1    = (const float*)d_in[13];
    const float* b1    = (const float*)d_in[14];
    const float* W2    = (const float*)d_in[15];
    const float* b2    = (const float*)d_in[16];
    const float* ln2g  = (const float*)d_in[17];
    const float* ln2b  = (const float*)d_in[18];
    float* out = (float*)d_out;

    float *Qp, *Kp, *Vp, *att, *x, *h1, *f1;
    cudaGetSymbolAddress((void**)&Qp,  g_Qp);
    cudaGetSymbolAddress((void**)&Kp,  g_Kp);
    cudaGetSymbolAddress((void**)&Vp,  g_Vp);
    cudaGetSymbolAddress((void**)&att, g_att);
    cudaGetSymbolAddress((void**)&x,   g_x);
    cudaGetSymbolAddress((void**)&h1,  g_h1);
    cudaGetSymbolAddress((void**)&f1,  g_f1);

    // Q/K/V projections
    gemm_bias_kernel<<<dim3(Hdim / 64, M_Q  / 64), 256>>>(query, Wq, bq, Qp, M_Q,  Hdim, Hdim, 0);
    gemm_bias_kernel<<<dim3(Hdim / 64, M_KV / 64), 256>>>(key,   Wk, bk, Kp, M_KV, Hdim, Hdim, 0);
    gemm_bias_kernel<<<dim3(Hdim / 64, M_KV / 64), 256>>>(value, Wv, bv, Vp, M_KV, Hdim, Hdim, 0);

    // attention (S=8 per row)
    attn_kernel<<<M_Q, 256>>>(Qp, Kp, Vp, att);

    // O projection + residual + LN1
    gemm_bias_kernel<<<dim3(Hdim / 64, M_Q / 64), 256>>>(att, Wo, bo, x, M_Q, Hdim, Hdim, 0);
    ln_residual_kernel<<<M_Q, 256>>>(x, query, ln1g, ln1b, h1);

    // FFN + residual + LN2 (writes final output)
    gemm_bias_kernel<<<dim3(HF   / 64, M_Q / 64), 256>>>(h1, W1, b1, f1, M_Q, HF,   Hdim, 1);
    gemm_bias_kernel<<<dim3(Hdim / 64, M_Q / 64), 256>>>(f1, W2, b2, x,  M_Q, Hdim, HF,   0);
    ln_residual_kernel<<<M_Q, 256>>>(x, h1, ln2g, ln2b, out);
}

// round 3
// speedup vs baseline: 4.1600x; 4.1600x over previous
#include <cuda_runtime.h>
#include <cuda_bf16.h>
#include <cstdint>

// ---------------------------------------------------------------------------
// AttentionEncoderLayer: B=4, C=8, F=2048, H=512, NH=8, dh=64, Hf=1024
//   M = F*B = 8192 query rows; key/value flat [65536,512];
//   query row m attends KV rows [8m, 8m+8).
// GEMMs: HMMA (mma.sync bf16, baseline PTX -> works at compute_103) with
// 3-pass split-bf16: x = hi + lo;  A*B ~= Ah*Bh + Ah*Bl + Al*Bh, fp32 accum.
// ---------------------------------------------------------------------------

#define M_Q   8192
#define M_KV  65536
#define Hdim  512
#define HF    1024

__device__ float g_Qp [M_Q  * Hdim];
__device__ float g_Kp [M_KV * Hdim];
__device__ float g_Vp [M_KV * Hdim];
__device__ float g_att[M_Q  * Hdim];
__device__ float g_x  [M_Q  * Hdim];
__device__ float g_h1 [M_Q  * Hdim];
__device__ float g_f1 [M_Q  * HF  ];

// ---------------- helpers ----------------
__device__ __forceinline__ uint32_t smem_u32(const void* p) {
    uint32_t a;
    asm("{ .reg .u64 t; cvta.to.shared.u64 t, %1; cvt.u32.u64 %0, t; }" : "=r"(a) : "l"(p));
    return a;
}

__device__ __forceinline__ void ldsm4(uint32_t* r, uint32_t addr) {
    asm volatile("ldmatrix.sync.aligned.m8n8.x4.shared.b16 {%0,%1,%2,%3}, [%4];"
                 : "=r"(r[0]), "=r"(r[1]), "=r"(r[2]), "=r"(r[3]) : "r"(addr));
}

__device__ __forceinline__ void mma16816(float* d, const uint32_t* a, const uint32_t* b) {
    asm volatile("mma.sync.aligned.m16n8k16.row.col.f32.bf16.bf16.f32 "
                 "{%0,%1,%2,%3}, {%4,%5,%6,%7}, {%8,%9}, {%0,%1,%2,%3};"
                 : "+f"(d[0]), "+f"(d[1]), "+f"(d[2]), "+f"(d[3])
                 : "r"(a[0]), "r"(a[1]), "r"(a[2]), "r"(a[3]), "r"(b[0]), "r"(b[1]));
}

// ---------------------------------------------------------------------------
// HMMA GEMM: C[M,N] = A[M,K] @ W[N,K]^T + bias (opt relu)
// Tile 128x128, BK=64 chunks, 256 threads (8 warps, each 64x32).
// SMEM per buffer: Ah, Al, Bh, Bl tiles, each 128 rows x 64 bf16 (=128B/row),
// XOR-swizzled within 8-row groups. Double buffered: 8 * 16KB = 128KB.
// Requires M%128==0, N%128==0, K%64==0 (true for all shapes here).
// ---------------------------------------------------------------------------
#define TILE_B   16384
#define SMEM_GEMM (8 * TILE_B)   // 131072

// global (fp32) -> registers: 8 x float4 per thread (one 128x64 fp32 tile / 256 thr)
__device__ __forceinline__ void ldg8(const float* __restrict__ src, int ldk,
                                     int row0, int k0, int g, int c4, float4* v)
{
#pragma unroll
    for (int i = 0; i < 8; i++)
        v[i] = *(const float4*)(src + (size_t)(row0 + g * 8 + i) * ldk + k0 + c4 * 4);
}

// registers -> bf16 hi/lo swizzled smem tiles
__device__ __forceinline__ void cvsts8(const float4* v, char* __restrict__ hb,
                                       char* __restrict__ lb, int g, int c4)
{
#pragma unroll
    for (int i = 0; i < 8; i++) {
        const int r = g * 8 + i;
        const float4 x = v[i];

        uint32_t h01, h23;
        asm("cvt.rn.bf16x2.f32 %0, %1, %2;" : "=r"(h01) : "f"(x.y), "f"(x.x));
        asm("cvt.rn.bf16x2.f32 %0, %1, %2;" : "=r"(h23) : "f"(x.w), "f"(x.z));

        const float hf0 = __uint_as_float(h01 << 16);
        const float hf1 = __uint_as_float(h01 & 0xffff0000u);
        const float hf2 = __uint_as_float(h23 << 16);
        const float hf3 = __uint_as_float(h23 & 0xffff0000u);

        uint32_t l01, l23;
        asm("cvt.rn.bf16x2.f32 %0, %1, %2;" : "=r"(l01) : "f"(x.y - hf1), "f"(x.x - hf0));
        asm("cvt.rn.bf16x2.f32 %0, %1, %2;" : "=r"(l23) : "f"(x.w - hf3), "f"(x.z - hf2));

        const int off = r * 128 + ((c4 * 8) ^ ((r & 7) << 4));
        *(uint2*)(hb + off) = make_uint2(h01, h23);
        *(uint2*)(lb + off) = make_uint2(l01, l23);
    }
}

__global__ __launch_bounds__(256, 1)
void gemm_mma(const float* __restrict__ A, const float* __restrict__ W,
              const float* __restrict__ bias, float* __restrict__ C,
              int M, int N, int K, int relu)
{
    extern __shared__ char smem[];
    const uint32_t sb = smem_u32(smem);

    const int tid = threadIdx.x;
    const int w   = tid >> 5;
    const int l   = tid & 31;
    const int mw  = w & 1;      // 0/1  -> 64-row half
    const int nw  = w >> 1;     // 0..3 -> 32-col quarter
    const int m0  = blockIdx.y * 128;
    const int n0  = blockIdx.x * 128;
    const int g   = tid >> 4;   // loader row group
    const int c4  = tid & 15;   // loader col group

    // ldmatrix lane geometry (shared XOR swizzle)
    const uint32_t swz = (uint32_t)((l & 7) << 4);
    const uint32_t ak  = (uint32_t)((l >> 4) << 4);          // A k-half byte off
    const uint32_t bk  = (uint32_t)(((l >> 3) & 1) << 4);    // B k-half byte off
    uint32_t arow[4];
#pragma unroll
    for (int mt = 0; mt < 4; mt++)
        arow[mt] = (uint32_t)((mw * 64 + mt * 16 + (l & 15)) * 128);
    uint32_t brow[2];
#pragma unroll
    for (int nt2 = 0; nt2 < 2; nt2++)
        brow[nt2] = (uint32_t)((nw * 32 + nt2 * 16 + ((l >> 4) << 3) + (l & 7)) * 128);

    float acc[4][4][4];
#pragma unroll
    for (int i = 0; i < 4; i++)
#pragma unroll
        for (int j = 0; j < 4; j++)
#pragma unroll
            for (int q = 0; q < 4; q++) acc[i][j][q] = 0.f;

    const int NC = K >> 6;

    // prologue: chunk 0 -> buffer 0
    {
        float4 sa[8], sw4[8];
        ldg8(A, K, m0, 0, g, c4, sa);
        ldg8(W, K, n0, 0, g, c4, sw4);
        cvsts8(sa,  smem,              smem + TILE_B,     g, c4);
        cvsts8(sw4, smem + 2 * TILE_B, smem + 3 * TILE_B, g, c4);
    }
    __syncthreads();

    for (int c = 0; c < NC; c++) {
        const int b  = c & 1;
        const int nb = b ^ 1;
        const bool more = (c + 1 < NC);

        float4 sa[8], sw4[8];
        if (more) {
            ldg8(A, K, m0, (c + 1) << 6, g, c4, sa);
            ldg8(W, K, n0, (c + 1) << 6, g, c4, sw4);
        }

        const uint32_t bAh = sb + b * 4 * TILE_B;
        const uint32_t bAl = bAh + TILE_B;
        const uint32_t bBh = bAh + 2 * TILE_B;
        const uint32_t bBl = bAh + 3 * TILE_B;

#pragma unroll
        for (int kk = 0; kk < 4; kk++) {
            const uint32_t kbA = ((uint32_t)(kk * 32) | ak) ^ swz;
            const uint32_t kbB = ((uint32_t)(kk * 32) | bk) ^ swz;

            uint32_t bh[8], bl[8];
            ldsm4(bh + 0, bBh + brow[0] + kbB);
            ldsm4(bh + 4, bBh + brow[1] + kbB);
            ldsm4(bl + 0, bBl + brow[0] + kbB);
            ldsm4(bl + 4, bBl + brow[1] + kbB);

#pragma unroll
            for (int mt = 0; mt < 4; mt++) {
                uint32_t ah[4], al[4];
                ldsm4(ah, bAh + arow[mt] + kbA);
                ldsm4(al, bAl + arow[mt] + kbA);
#pragma unroll
                for (int nt = 0; nt < 4; nt++) mma16816(acc[mt][nt], ah, bh + nt * 2);
#pragma unroll
                for (int nt = 0; nt < 4; nt++) mma16816(acc[mt][nt], ah, bl + nt * 2);
#pragma unroll
                for (int nt = 0; nt < 4; nt++) mma16816(acc[mt][nt], al, bh + nt * 2);
            }
        }

        if (more) {
            char* base = smem + nb * 4 * TILE_B;
            cvsts8(sa,  base,              base + TILE_B,     g, c4);
            cvsts8(sw4, base + 2 * TILE_B, base + 3 * TILE_B, g, c4);
        }
        __syncthreads();
    }

    // epilogue: registers -> C with bias (+relu)
    const int row_base = m0 + mw * 64 + (l >> 2);
    const int col_base = n0 + nw * 32 + 2 * (l & 3);
#pragma unroll
    for (int mt = 0; mt < 4; mt++) {
        const int row = row_base + mt * 16;
#pragma unroll
        for (int nt = 0; nt < 4; nt++) {
            const int col = col_base + nt * 8;
            const float2 bv = *(const float2*)(bias + col);
            float2 r0, r1;
            r0.x = acc[mt][nt][0] + bv.x;  r0.y = acc[mt][nt][1] + bv.y;
            r1.x = acc[mt][nt][2] + bv.x;  r1.y = acc[mt][nt][3] + bv.y;
            if (relu) {
                r0.x = fmaxf(r0.x, 0.f); r0.y = fmaxf(r0.y, 0.f);
                r1.x = fmaxf(r1.x, 0.f); r1.y = fmaxf(r1.y, 0.f);
            }
            *(float2*)(C + (size_t)row * N + col)       = r0;
            *(float2*)(C + (size_t)(row + 8) * N + col) = r1;
        }
    }
}

// ---------------------------------------------------------------------------
// Attention: one block per query row m, warp = head. S=8, dh=64, scale=0.125
// ---------------------------------------------------------------------------
__global__ __launch_bounds__(256)
void attn_kernel(const float* __restrict__ Qp, const float* __restrict__ Kp,
                 const float* __restrict__ Vp, float* __restrict__ out)
{
    const int m = blockIdx.x;
    const int w = threadIdx.x >> 5;
    const int l = threadIdx.x & 31;

    const size_t qoff = (size_t)m * Hdim + w * 64;
    const float q0 = Qp[qoff + l];
    const float q1 = Qp[qoff + l + 32];

    float s[8];
#pragma unroll
    for (int c = 0; c < 8; c++) {
        const float* k = Kp + ((size_t)m * 8 + c) * Hdim + w * 64;
        float p = q0 * k[l] + q1 * k[l + 32];
#pragma unroll
        for (int o = 16; o > 0; o >>= 1)
            p += __shfl_xor_sync(0xffffffffu, p, o);
        s[c] = p * 0.125f;
    }

    float mx = s[0];
#pragma unroll
    for (int c = 1; c < 8; c++) mx = fmaxf(mx, s[c]);
    float sum = 0.f;
#pragma unroll
    for (int c = 0; c < 8; c++) { s[c] = __expf(s[c] - mx); sum += s[c]; }
    const float inv = 1.f / sum;

    float o0 = 0.f, o1 = 0.f;
#pragma unroll
    for (int c = 0; c < 8; c++) {
        const float* v = Vp + ((size_t)m * 8 + c) * Hdim + w * 64;
        const float p = s[c] * inv;
        o0 += p * v[l];
        o1 += p * v[l + 32];
    }
    out[qoff + l]      = o0;
    out[qoff + l + 32] = o1;
}

// ---------------------------------------------------------------------------
// LayerNorm(x + r) over H=512, one block (256 threads) per row.
// ---------------------------------------------------------------------------
__global__ __launch_bounds__(256)
void ln_residual_kernel(const float* __restrict__ x, const float* __restrict__ r,
                        const float* __restrict__ g, const float* __restrict__ bt,
                        float* __restrict__ out)
{
    __shared__ float red[256];
    const int m = blockIdx.x;
    const int t = threadIdx.x;
    const size_t base = (size_t)m * Hdim;

    const float s0 = x[base + t]       + r[base + t];
    const float s1 = x[base + t + 256] + r[base + t + 256];

    red[t] = s0 + s1;
    __syncthreads();
#pragma unroll
    for (int o = 128; o > 0; o >>= 1) {
        if (t < o) red[t] += red[t + o];
        __syncthreads();
    }
    const float mean = red[0] * (1.f / 512.f);
    __syncthreads();

    const float d0 = s0 - mean, d1 = s1 - mean;
    red[t] = d0 * d0 + d1 * d1;
    __syncthreads();
#pragma unroll
    for (int o = 128; o > 0; o >>= 1) {
        if (t < o) red[t] += red[t + o];
        __syncthreads();
    }
    const float var  = red[0] * (1.f / 512.f);
    const float rstd = rsqrtf(var + 1e-5f);

    out[base + t]       = d0 * rstd * g[t]       + bt[t];
    out[base + t + 256] = d1 * rstd * g[t + 256] + bt[t + 256];
}

// ---------------------------------------------------------------------------
extern "C" void kernel_launch(void* const* d_in, const int* in_sizes, int n_in,
                              void* d_out, int out_size)
{
    (void)in_sizes; (void)n_in; (void)out_size;
    const float* query = (const float*)d_in[0];
    const float* key   = (const float*)d_in[1];
    const float* value = (const float*)d_in[2];
    const float* Wq    = (const float*)d_in[3];
    const float* bq    = (const float*)d_in[4];
    const float* Wk    = (const float*)d_in[5];
    const float* bk    = (const float*)d_in[6];
    const float* Wv    = (const float*)d_in[7];
    const float* bv    = (const float*)d_in[8];
    const float* Wo    = (const float*)d_in[9];
    const float* bo    = (const float*)d_in[10];
    const float* ln1g  = (const float*)d_in[11];
    const float* ln1b  = (const float*)d_in[12];
    const float* W1    = (const float*)d_in[13];
    const float* b1    = (const float*)d_in[14];
    const float* W2    = (const float*)d_in[15];
    const float* b2    = (const float*)d_in[16];
    const float* ln2g  = (const float*)d_in[17];
    const float* ln2b  = (const float*)d_in[18];
    float* out = (float*)d_out;

    float *Qp, *Kp, *Vp, *att, *x, *h1, *f1;
    cudaGetSymbolAddress((void**)&Qp,  g_Qp);
    cudaGetSymbolAddress((void**)&Kp,  g_Kp);
    cudaGetSymbolAddress((void**)&Vp,  g_Vp);
    cudaGetSymbolAddress((void**)&att, g_att);
    cudaGetSymbolAddress((void**)&x,   g_x);
    cudaGetSymbolAddress((void**)&h1,  g_h1);
    cudaGetSymbolAddress((void**)&f1,  g_f1);

    cudaFuncSetAttribute(gemm_mma, cudaFuncAttributeMaxDynamicSharedMemorySize, SMEM_GEMM);

    // Q/K/V projections
    gemm_mma<<<dim3(Hdim/128, M_Q /128), 256, SMEM_GEMM>>>(query, Wq, bq, Qp, M_Q,  Hdim, Hdim, 0);
    gemm_mma<<<dim3(Hdim/128, M_KV/128), 256, SMEM_GEMM>>>(key,   Wk, bk, Kp, M_KV, Hdim, Hdim, 0);
    gemm_mma<<<dim3(Hdim/128, M_KV/128), 256, SMEM_GEMM>>>(value, Wv, bv, Vp, M_KV, Hdim, Hdim, 0);

    // attention (S=8 per row)
    attn_kernel<<<M_Q, 256>>>(Qp, Kp, Vp, att);

    // O projection + residual + LN1
    gemm_mma<<<dim3(Hdim/128, M_Q/128), 256, SMEM_GEMM>>>(att, Wo, bo, x, M_Q, Hdim, Hdim, 0);
    ln_residual_kernel<<<M_Q, 256>>>(x, query, ln1g, ln1b, h1);

    // FFN + residual + LN2 (writes final output)
    gemm_mma<<<dim3(HF  /128, M_Q/128), 256, SMEM_GEMM>>>(h1, W1, b1, f1, M_Q, HF,   Hdim, 1);
    gemm_mma<<<dim3(Hdim/128, M_Q/128), 256, SMEM_GEMM>>>(f1, W2, b2, x,  M_Q, Hdim, HF,   0);
    ln_residual_kernel<<<M_Q, 256>>>(x, h1, ln2g, ln2b, out);
}